// round 16
// baseline (speedup 1.0000x reference)
#include <cuda_runtime.h>
#include <cstdint>

#define TM1 262143            // T-1 real output timesteps
#define RTILE 16              // recurrence pre-staging tile (steps)
#define NTILES_R 16384        // 16384*16 = 262144 steps (1 pad step)
#define PRE_TCHUNK 128
#define CHUNK 256             // stage-B chunk (steps)
#define NCHUNKS ((TM1 + CHUNK - 1) / CHUNK)   // 1024
#define NB 6                  // stage-B helper CTAs
#define GRID_MEGA (2 + NB)

typedef unsigned long long ull;

// Scratch. pre buffers padded one extra tile so tile prefetch never branches;
// h traces padded for the pad step. Pads stay zero.
// pre layout is TRANSPOSED within each step: index = t*256 + u*4 + gate
// (conflict-free LDS in the recurrence: bank = (4k+g) mod 32, a bijection).
__device__ float g_pre0[(size_t)(TM1 + 2 * RTILE + 2) * 256];
__device__ float g_h0[(size_t)(TM1 + 32) * 64];
__device__ float g_pre1[(size_t)(TM1 + 2 * RTILE + 2) * 256];
__device__ float g_h2[(size_t)(TM1 + 32) * 64];
__device__ int   g_progA;
__device__ int   g_chunk_done[NCHUNKS];

#define LOG2E    1.4426950408889634f
#define TWOLOG2E 2.8853900817779268f

// perm: gate-row r -> transposed in-step index u*4+g
#define PERM(r) ((((r) & 63) << 2) | ((r) >> 6))

// ---------------- fast math helpers ----------------
__device__ __forceinline__ void ffma2(ull& acc, ull a, ull b) {
    asm("fma.rn.f32x2 %0, %1, %2, %0;" : "+l"(acc) : "l"(a), "l"(b));
}
__device__ __forceinline__ ull packf2(float x, float y) {
    ull r; asm("mov.b64 %0, {%1, %2};" : "=l"(r) : "f"(x), "f"(y)); return r;
}
__device__ __forceinline__ ull addf2(ull a, ull b) {
    ull r; asm("add.rn.f32x2 %0, %1, %2;" : "=l"(r) : "l"(a), "l"(b)); return r;
}
__device__ __forceinline__ float hsum_final(ull s) {
    float lo, hi;
    asm("mov.b64 {%0,%1}, %2;" : "=f"(lo), "=f"(hi) : "l"(s));
    return lo + hi;
}
__device__ __forceinline__ float fast_ex2(float x) {
    float r; asm("ex2.approx.f32 %0, %1;" : "=f"(r) : "f"(x)); return r;
}
__device__ __forceinline__ float fast_rcp(float x) {
    float r; asm("rcp.approx.f32 %0, %1;" : "=f"(r) : "f"(x)); return r;
}

// ---------------- cross-CTA sync ----------------
__device__ __forceinline__ int ld_acq(const int* p) {
    int v; asm volatile("ld.global.acquire.gpu.b32 %0, [%1];" : "=r"(v) : "l"(p)); return v;
}
__device__ __forceinline__ void st_rel(int* p, int v) {
    asm volatile("st.global.release.gpu.b32 [%0], %1;" :: "l"(p), "r"(v) : "memory");
}

// ---------------- cp.async (LDGSTS) ----------------
__device__ __forceinline__ void cpasync16(unsigned int sdst, const void* gsrc) {
    asm volatile("cp.async.cg.shared.global [%0], [%1], 16;" :: "r"(sdst), "l"(gsrc));
}
__device__ __forceinline__ void cpasync_commit() {
    asm volatile("cp.async.commit_group;" ::: "memory");
}
__device__ __forceinline__ void cpasync_wait_all() {
    asm volatile("cp.async.wait_group 0;" ::: "memory");
}

// 64-dot, 4 chains (stage B; latency uncritical there)
__device__ __forceinline__ float dot64(const ull* __restrict__ w, const float* __restrict__ hvec) {
    ull a0 = 0ull, a1 = 0ull, a2 = 0ull, a3 = 0ull;
    const ulonglong2* hp = (const ulonglong2*)hvec;
#pragma unroll
    for (int i = 0; i < 16; i += 2) {
        ulonglong2 va = hp[i];
        ulonglong2 vb = hp[i + 1];
        ffma2(a0, w[2 * i],     va.x);
        ffma2(a1, w[2 * i + 1], va.y);
        ffma2(a2, w[2 * i + 2], vb.x);
        ffma2(a3, w[2 * i + 3], vb.y);
    }
    return hsum_final(addf2(addf2(a0, a1), addf2(a2, a3)));
}

// ---------------- init: reset cross-CTA sync state (graph replays!) ----------------
__global__ void init_sync_kernel() {
    int i = blockIdx.x * blockDim.x + threadIdx.x;
    if (i == 0) g_progA = 0;
    if (i < NCHUNKS) g_chunk_done[i] = 0;
}

// ---------------- phase 1: layer0 input-side preactivations (am-prescaled, permuted) ----------------
__global__ __launch_bounds__(256)
void pre0_kernel(const float* __restrict__ y,
                 const float* __restrict__ Wih0,
                 const float* __restrict__ bih0,
                 const float* __restrict__ bhh0)
{
    __shared__ float sy[PRE_TCHUNK + 8];
    const int r = threadIdx.x;
    const int t0 = blockIdx.x * PRE_TCHUNK;
    int t1 = t0 + PRE_TCHUNK; if (t1 > TM1) t1 = TM1;

    for (int i = r; i < PRE_TCHUNK + 5; i += 256) {
        int idx = t0 + i;                    // padded index
        sy[i] = (idx < 5) ? 1.0f : y[idx - 5];
    }

    float w[6];
#pragma unroll
    for (int j = 0; j < 6; j++) w[j] = Wih0[r * 6 + j];
    const float b = bih0[r] + bhh0[r];
    const float am = ((r >> 6) == 2) ? TWOLOG2E : -LOG2E;
    const int pr = PERM(r);
    __syncthreads();

    for (int t = t0; t < t1; t++) {
        float acc = b;
#pragma unroll
        for (int j = 0; j < 6; j++)
            acc = fmaf(w[j], sy[t - t0 + j], acc);
        g_pre0[(size_t)t * 256 + pr] = am * acc;
    }
}

// ============ recurrence core ============
// Lane mapping: warp w, lane l -> gate g=l>>3, unit u=8w+(l&7), gate-row r=64g+u.
// pre stream (am-scaled, permuted) staged via cp.async in 16-step tiles.
template<bool IS_C>
__device__ void recurrence(const float* __restrict__ Whh,
                           const float* __restrict__ preBuf,
                           float* __restrict__ hTrace)
{
    __shared__ __align__(16) float shb[2][64];
    __shared__ __align__(16) float spre[2][RTILE * 256];   // 2 x 16KB
    const int tid = threadIdx.x;
    const int wv  = tid >> 5;
    const int l   = tid & 31;
    const int g   = l >> 3;
    const int u8  = l & 7;
    const int u   = 8 * wv + u8;
    const int r   = 64 * g + u;

    const float am = (g == 2) ? TWOLOG2E : -LOG2E;
    const float aa = (g == 2) ? 1.0f : 0.0f;
    const float ab = (g == 2) ? -2.0f : 1.0f;

    // weights pre-scaled by am
    ull w[32];
    {
        const float2* p = (const float2*)(Whh + r * 64);
#pragma unroll
        for (int i = 0; i < 32; i++) {
            float2 f = p[i];
            w[i] = packf2(am * f.x, am * f.y);
        }
    }

    if (l < 8) shb[0][u] = 0.0f;
    float c = 0.0f;

    if (IS_C) {
        while (ld_acq(&g_chunk_done[0]) == 0) __nanosleep(256);
    }
    // prologue: stage tile 0 (16KB; 4 x 16B per thread)
    {
        const float* src = preBuf + (size_t)tid * 4;
        unsigned int d = (unsigned int)__cvta_generic_to_shared(&spre[0][0]);
#pragma unroll
        for (int j = 0; j < 4; j++)
            cpasync16(d + (tid + 256 * j) * 16, src + 1024 * j);
        cpasync_commit();
        cpasync_wait_all();
    }
    __syncthreads();

    float* hp = hTrace + u;
    const int pidx = u * 4 + g;          // conflict-free transposed pre index

    for (int tile = 0; tile < NTILES_R; tile++) {
        if (IS_C) {
            if (((tile + 1) & 15) == 0) {
                int ch = (tile + 1) >> 4;
                if (ch > NCHUNKS - 1) ch = NCHUNKS - 1;
                while (ld_acq(&g_chunk_done[ch]) == 0) __nanosleep(128);
            }
        }
        // prefetch tile+1 (waited ~16 steps later)
        {
            const float* src = preBuf + (size_t)(tile + 1) * (RTILE * 256) + tid * 4;
            unsigned int d = (unsigned int)__cvta_generic_to_shared(&spre[(tile + 1) & 1][0]);
#pragma unroll
            for (int j = 0; j < 4; j++)
                cpasync16(d + (tid + 256 * j) * 16, src + 1024 * j);
            cpasync_commit();
        }

        const float* pt = &spre[tile & 1][pidx];
        float htr[RTILE];                 // per-tile trace batch (lanes l<8 use it)

#pragma unroll
        for (int s = 0; s < RTILE; s++) {
            const float pre = pt[s * 256];            // conflict-free LDS

            // 8-chain dot (depth 4) over the FULL 64-vector: hv[0..15], w[0..31]
            ull a0 = 0ull, a1 = 0ull, a2 = 0ull, a3 = 0ull;
            ull b0 = 0ull, b1 = 0ull, b2 = 0ull, b3 = 0ull;
            {
                const ulonglong2* hv = (const ulonglong2*)shb[s & 1];
#pragma unroll
                for (int i = 0; i < 16; i += 4) {
                    ulonglong2 v0 = hv[i], v1 = hv[i + 1], v2 = hv[i + 2], v3 = hv[i + 3];
                    ffma2(a0, w[2 * i],     v0.x); ffma2(b0, w[2 * i + 1], v0.y);
                    ffma2(a1, w[2 * i + 2], v1.x); ffma2(b1, w[2 * i + 3], v1.y);
                    ffma2(a2, w[2 * i + 4], v2.x); ffma2(b2, w[2 * i + 5], v2.y);
                    ffma2(a3, w[2 * i + 6], v3.x); ffma2(b3, w[2 * i + 7], v3.y);
                }
            }
            const ull s0 = addf2(addf2(a0, a1), addf2(a2, a3));
            const ull s1 = addf2(addf2(b0, b1), addf2(b2, b3));
            const float v = pre + hsum_final(addf2(s0, s1));   // am-scaled

            const float e   = fast_ex2(v);
            const float act = fmaf(ab, fast_rcp(e + 1.0f), aa);
            const float gi = __shfl_sync(0xffffffffu, act, u8);
            const float gf = __shfl_sync(0xffffffffu, act, u8 + 8);
            const float gg = __shfl_sync(0xffffffffu, act, u8 + 16);
            const float go = __shfl_sync(0xffffffffu, act, u8 + 24);
            c = fmaf(gf, c, gi * gg);
            const float tg = 2.0f * go;               // off-path
            const float e2 = fast_ex2(TWOLOG2E * c);
            const float h  = fmaf(-tg, fast_rcp(e2 + 1.0f), go);   // go*tanh(c)

            htr[s] = h;
            if (l < 8) shb[(s + 1) & 1][u] = h;       // predicated short store
            __syncthreads();
        }

        // batched trace store: 4 x STG.128 per owning lane
        if (l < 8) {
#pragma unroll
            for (int s = 0; s < RTILE; s++)
                hp[s * 64] = htr[s];
        }
        hp += RTILE * 64;

        cpasync_wait_all();      // tile+1 staged (issued ~16 steps ago)
        __syncthreads();

        if (!IS_C) {
            if (((tile & 3) == 3) && tid == 0) {      // publish every 64 steps
                __threadfence();
                st_rel(&g_progA, (tile + 1) * RTILE);
            }
        }
    }
}

// ---------------- stage B: pre1[t] = am*(b1 + W_ih1 . h0[t])  (permuted store) ----------------
__device__ void stageB(int helper,
                       const float* __restrict__ Wih1,
                       const float* __restrict__ bih1,
                       const float* __restrict__ bhh1)
{
    __shared__ __align__(16) float sh[64 * 64];   // 64-step tile of h0
    const int r = threadIdx.x;

    ull w[32];
    {
        const ull* p = (const ull*)(Wih1 + r * 64);
#pragma unroll
        for (int i = 0; i < 32; i++) w[i] = p[i];
    }
    const float b1 = bih1[r] + bhh1[r];
    const float am = ((r >> 6) == 2) ? TWOLOG2E : -LOG2E;
    const int pr = PERM(r);

    for (int c = helper; c < NCHUNKS; c += NB) {
        const int t0 = c * CHUNK;
        int t1 = t0 + CHUNK; if (t1 > TM1) t1 = TM1;

        while (ld_acq(&g_progA) < t1) __nanosleep(256);

        for (int tb = t0; tb < t1; tb += 64) {
            const int cnt = min(64, t1 - tb);
            __syncthreads();
            for (int i = r; i < cnt * 64; i += 256)
                sh[i] = g_h0[(size_t)tb * 64 + i];
            __syncthreads();
            for (int tt = 0; tt < cnt; tt++)
                g_pre1[(size_t)(tb + tt) * 256 + pr] = am * (b1 + dot64(w, sh + tt * 64));
        }
        __syncthreads();
        if (r == 0) { __threadfence(); st_rel(&g_chunk_done[c], 1); }
    }
}

// ---------------- pipelined serial phase: 8 co-resident CTAs ----------------
__global__ __launch_bounds__(256, 1)
void lstm_pipe_kernel(const float* __restrict__ Whh0,
                      const float* __restrict__ Wih1,
                      const float* __restrict__ Whh1,
                      const float* __restrict__ bih1,
                      const float* __restrict__ bhh1)
{
    if (blockIdx.x == 0)       recurrence<false>(Whh0, g_pre0, g_h0);
    else if (blockIdx.x == 1)  recurrence<true >(Whh1, g_pre1, g_h2);
    else                       stageB(blockIdx.x - 2, Wih1, bih1, bhh1);
}

// ---------------- phase 3: parallel FC head ----------------
__global__ __launch_bounds__(256)
void fc_kernel(const float* __restrict__ Wfc,
               const float* __restrict__ bfc,
               float* __restrict__ out)
{
    __shared__ float sWT[64 * 64];
    __shared__ float sh[64 * 64];

    const int tid = threadIdx.x;
    for (int i = tid; i < 4096; i += 256) {
        int n = i >> 6, k = i & 63;
        sWT[k * 64 + n] = Wfc[i];
    }
    const int tbase = blockIdx.x * 64;
    for (int i = tid; i < 4096; i += 256) {
        int tt = i >> 6, k = i & 63;
        int t = tbase + tt;
        sh[i] = (t < TM1) ? g_h2[(size_t)t * 64 + k] : 0.0f;
    }
    __syncthreads();

    const int n = tid & 63;
    const float bb = bfc[n];
    for (int tt = tid >> 6; tt < 64; tt += 4) {
        const int t = tbase + tt;
        if (t >= TM1) break;
        float acc = bb;
#pragma unroll
        for (int k = 0; k < 64; k++)
            acc = fmaf(sh[tt * 64 + k], sWT[k * 64 + n], acc);
        out[(size_t)t * 64 + n] = acc;
    }
}

// ---------------- launch ----------------
extern "C" void kernel_launch(void* const* d_in, const int* in_sizes, int n_in,
                              void* d_out, int out_size)
{
    const float* y    = (const float*)d_in[0];
    const float* Wih0 = (const float*)d_in[1];
    const float* Whh0 = (const float*)d_in[2];
    const float* bih0 = (const float*)d_in[3];
    const float* bhh0 = (const float*)d_in[4];
    const float* Wih1 = (const float*)d_in[5];
    const float* Whh1 = (const float*)d_in[6];
    const float* bih1 = (const float*)d_in[7];
    const float* bhh1 = (const float*)d_in[8];
    const float* Wfc  = (const float*)d_in[9];
    const float* bfc  = (const float*)d_in[10];
    float* out = (float*)d_out;

    init_sync_kernel<<<4, 256>>>();
    const int preblocks = (TM1 + PRE_TCHUNK - 1) / PRE_TCHUNK;
    pre0_kernel<<<preblocks, 256>>>(y, Wih0, bih0, bhh0);
    lstm_pipe_kernel<<<GRID_MEGA, 256>>>(Whh0, Wih1, Whh1, bih1, bhh1);
    fc_kernel<<<(TM1 + 63) / 64, 256>>>(Wfc, bfc, out);
}